// round 11
// baseline (speedup 1.0000x reference)
#include <cuda_runtime.h>
#include <cstdint>

// ---------------------------------------------------------------------------
// APPNP. GEMM1: tf32 mma.sync, 3-stage pipeline. B (W1) pre-rounded to tf32
// once and staged via cp.async (no in-loop cvt); A staged via LDG->cvt.rna->STS
// with 2-chunk register prefetch (cvt outside the mma loop).
// Propagation: CSR(dst) + fused gather-reduce, natural node order.
// ---------------------------------------------------------------------------

#define N_NODES 100000
#define E_EDGES 1600000
#define OUT_DIM 48
#define HID_DIM 256
#define IN_DIM  512

// Scratch (device globals — allocation APIs are forbidden)
__device__ __align__(16) float g_hidden[(size_t)N_NODES * HID_DIM];
__device__ __align__(16) float g_w1r[(size_t)IN_DIM * HID_DIM];   // tf32-rounded W1
__device__ __align__(16) float g_h0[(size_t)N_NODES * OUT_DIM];
__device__ __align__(16) float g_hsA[(size_t)N_NODES * OUT_DIM];
__device__ __align__(16) float g_hsB[(size_t)N_NODES * OUT_DIM];
__device__ int   g_ideg_out[N_NODES];
__device__ int   g_ideg_in[N_NODES];
__device__ float g_norm_out[N_NODES];
__device__ float g_norm_in[N_NODES];
__device__ int   g_off[N_NODES + 1];
__device__ int   g_cursor[N_NODES];
__device__ int   g_blocksums[512];
__device__ int   g_csr_src[E_EDGES];

// ---------------------------------------------------------------------------
// Degrees / norms
// ---------------------------------------------------------------------------
__global__ void zero_deg_kernel(int n) {
    int i = blockIdx.x * blockDim.x + threadIdx.x;
    if (i < n) { g_ideg_out[i] = 0; g_ideg_in[i] = 0; }
}
__global__ void deg_kernel(const int* __restrict__ src, const int* __restrict__ dst, int e) {
    int i = blockIdx.x * blockDim.x + threadIdx.x;
    if (i < e) {
        atomicAdd(&g_ideg_out[src[i]], 1);
        atomicAdd(&g_ideg_in[dst[i]], 1);
    }
}
__global__ void norm_kernel(int n) {
    int i = blockIdx.x * blockDim.x + threadIdx.x;
    if (i < n) {
        g_norm_out[i] = rsqrtf((float)max(g_ideg_out[i], 1));
        g_norm_in[i]  = rsqrtf((float)max(g_ideg_in[i], 1));
    }
}

// ---------------------------------------------------------------------------
// Prefix sum over g_ideg_in -> g_off
// ---------------------------------------------------------------------------
__global__ void scanA_kernel(int n) {
    __shared__ int sh[256];
    int i = blockIdx.x * 256 + threadIdx.x;
    sh[threadIdx.x] = (i < n) ? g_ideg_in[i] : 0;
    __syncthreads();
#pragma unroll
    for (int d = 1; d < 256; d <<= 1) {
        int t = (threadIdx.x >= d) ? sh[threadIdx.x - d] : 0;
        __syncthreads();
        sh[threadIdx.x] += t;
        __syncthreads();
    }
    if (i < n) g_off[i + 1] = sh[threadIdx.x];
    if (threadIdx.x == 255) g_blocksums[blockIdx.x] = sh[255];
}
__global__ void scanB_kernel(int nb) {
    __shared__ int sh[512];
    int t = threadIdx.x;
    sh[t] = (t < nb) ? g_blocksums[t] : 0;
    __syncthreads();
#pragma unroll
    for (int d = 1; d < 512; d <<= 1) {
        int x = (t >= d) ? sh[t - d] : 0;
        __syncthreads();
        sh[t] += x;
        __syncthreads();
    }
    if (t < nb) g_blocksums[t] = sh[t];
}
__global__ void scanC_kernel(int n) {
    int i = blockIdx.x * 256 + threadIdx.x;
    if (i < n) {
        int add = (blockIdx.x > 0) ? g_blocksums[blockIdx.x - 1] : 0;
        g_off[i + 1] += add;
    }
    if (i == 0) g_off[0] = 0;
}
__global__ void cursor_init_kernel(int n) {
    int i = blockIdx.x * blockDim.x + threadIdx.x;
    if (i < n) g_cursor[i] = g_off[i];
}
__global__ void scatter_kernel(const int* __restrict__ src, const int* __restrict__ dst, int e) {
    int i = blockIdx.x * blockDim.x + threadIdx.x;
    if (i < e) {
        int p = atomicAdd(&g_cursor[dst[i]], 1);
        g_csr_src[p] = src[i];
    }
}

// ---------------------------------------------------------------------------
// tf32 helpers
// ---------------------------------------------------------------------------
__device__ __forceinline__ uint32_t rna_tf32_f(float x) {
    uint32_t u;
    asm("cvt.rna.tf32.f32 %0, %1;" : "=r"(u) : "f"(x));
    return u;
}
__device__ __forceinline__ void mma_tf32(float c[4],
                                         uint32_t a0, uint32_t a1, uint32_t a2, uint32_t a3,
                                         uint32_t b0, uint32_t b1)
{
    asm volatile(
        "mma.sync.aligned.m16n8k8.row.col.f32.tf32.tf32.f32 "
        "{%0,%1,%2,%3}, {%4,%5,%6,%7}, {%8,%9}, {%0,%1,%2,%3};"
        : "+f"(c[0]), "+f"(c[1]), "+f"(c[2]), "+f"(c[3])
        : "r"(a0), "r"(a1), "r"(a2), "r"(a3), "r"(b0), "r"(b1));
}
__device__ __forceinline__ uint32_t smem_u32(const void* p) {
    uint32_t a;
    asm("{ .reg .u64 t; cvta.to.shared.u64 t, %1; cvt.u32.u64 %0, t; }" : "=r"(a) : "l"(p));
    return a;
}
__device__ __forceinline__ void cp16(uint32_t dst, const void* src) {
    asm volatile("cp.async.cg.shared.global [%0], [%1], 16;"
                 :: "r"(dst), "l"(src));
}
#define CP_COMMIT() asm volatile("cp.async.commit_group;" ::: "memory")
#define CP_WAIT(n)  asm volatile("cp.async.wait_group %0;" :: "n"(n) : "memory")

// ---------------------------------------------------------------------------
// W1 pre-round: g_w1r = rna_tf32(W1)   (mma's RZ truncation of this = identity)
// ---------------------------------------------------------------------------
__global__ void w1_round_kernel(const float* __restrict__ W1) {
    int i = blockIdx.x * blockDim.x + threadIdx.x;
    if (i < IN_DIM * HID_DIM)
        g_w1r[i] = __uint_as_float(rna_tf32_f(W1[i]));
}

// ---------------------------------------------------------------------------
// GEMM1 (tf32 mma.sync): hidden = relu(feats[M,512] @ W1[512,256] + b1)
// CTA tile 128x64, 8 warps (4 warpM x 2 warpN), warp tile 32x32.
// K chunks of 16, 3 SMEM stages. B via cp.async (pre-rounded, no cvt).
// A via LDG (2-chunk register prefetch) -> cvt.rna -> STS (cvt outside loop).
// ---------------------------------------------------------------------------
#define G1_AS_STRIDE 20
#define G1_BS_STRIDE 72
#define G1_NCHUNK    (IN_DIM / 16)   // 32... no: 512/16 = 32
// NOTE: NCHUNK = 32 chunks of K=16.

__global__ __launch_bounds__(256, 2) void gemm1_mma_kernel(
    const float* __restrict__ A, const float* __restrict__ bias, int M)
{
    __shared__ uint32_t As[3][128][G1_AS_STRIDE];
    __shared__ uint32_t Bs[3][16][G1_BS_STRIDE];

    const int tid  = threadIdx.x;
    const int wid  = tid >> 5;
    const int lane = tid & 31;
    const int warpM = wid & 3;
    const int warpN = wid >> 2;
    const int m0 = blockIdx.y * 128;
    const int n0 = blockIdx.x * 64;

    const int grp = lane >> 2;
    const int qid = lane & 3;

    // A staging coords: 2 float4 per thread per chunk
    const int a_m0  = tid >> 2;                 // 0..63
    const int a_k0  = (tid & 3) * 4;
    const int a_m1  = (tid + 256) >> 2;         // 64..127
    const int a_k1  = ((tid + 256) & 3) * 4;
    const bool a_ok0 = (m0 + a_m0 < M);
    const bool a_ok1 = (m0 + a_m1 < M);
    // B staging coords: 1 float4 per thread per chunk
    const int b_kk  = tid >> 4;
    const int b_nn4 = (tid & 15) * 4;

    float acc[2][4][4];
#pragma unroll
    for (int mt = 0; mt < 2; mt++)
#pragma unroll
        for (int nt = 0; nt < 4; nt++)
#pragma unroll
            for (int q = 0; q < 4; q++) acc[mt][nt][q] = 0.f;

    const int NCHUNK = IN_DIM / 16;  // 32

    // --- A register slots (2 chunks in flight) ---
    float4 slot[2][2];

    auto ldgA = [&](int kc, int s) {
        const int k0 = kc * 16;
        slot[s][0] = a_ok0 ? *(const float4*)&A[(size_t)(m0 + a_m0) * IN_DIM + k0 + a_k0]
                           : make_float4(0.f, 0.f, 0.f, 0.f);
        slot[s][1] = a_ok1 ? *(const float4*)&A[(size_t)(m0 + a_m1) * IN_DIM + k0 + a_k1]
                           : make_float4(0.f, 0.f, 0.f, 0.f);
    };
    auto stsA = [&](int b, int s) {
        uint4 v0, v1;
        v0.x = rna_tf32_f(slot[s][0].x); v0.y = rna_tf32_f(slot[s][0].y);
        v0.z = rna_tf32_f(slot[s][0].z); v0.w = rna_tf32_f(slot[s][0].w);
        v1.x = rna_tf32_f(slot[s][1].x); v1.y = rna_tf32_f(slot[s][1].y);
        v1.z = rna_tf32_f(slot[s][1].z); v1.w = rna_tf32_f(slot[s][1].w);
        *(uint4*)&As[b][a_m0][a_k0] = v0;
        *(uint4*)&As[b][a_m1][a_k1] = v1;
    };
    auto cpB = [&](int kc, int b) {
        const int k0 = kc * 16;
        cp16(smem_u32(&Bs[b][b_kk][b_nn4]),
             &g_w1r[(size_t)(k0 + b_kk) * HID_DIM + n0 + b_nn4]);
        CP_COMMIT();
    };

    // Prologue: stages 0..2 filled with chunks 0..2; slots hold chunks 3,4.
    ldgA(0, 0); ldgA(1, 1);
    stsA(0, 0); cpB(0, 0);
    ldgA(2, 0); stsA(1, 1); cpB(1, 1);
    ldgA(3, 1); stsA(2, 0); cpB(2, 2);
    ldgA(4, 0);

    int b = 0;
    for (int kc = 0; kc < NCHUNK; kc++) {
        // B for chunk kc ready: leave later groups outstanding
        if (kc < NCHUNK - 2)      { CP_WAIT(2); }
        else if (kc == NCHUNK - 2) { CP_WAIT(1); }
        else                       { CP_WAIT(0); }
        __syncthreads();

#pragma unroll
        for (int ks = 0; ks < 2; ks++) {
            const int k = ks * 8;
            uint32_t bf[4][2];
#pragma unroll
            for (int nt = 0; nt < 4; nt++) {
                int cn = warpN * 32 + nt * 8 + grp;
                bf[nt][0] = Bs[b][k + qid][cn];
                bf[nt][1] = Bs[b][k + 4 + qid][cn];
            }
#pragma unroll
            for (int mt = 0; mt < 2; mt++) {
                int rm = warpM * 32 + mt * 16 + grp;
                uint32_t a0 = As[b][rm][k + qid];
                uint32_t a1 = As[b][rm + 8][k + qid];
                uint32_t a2 = As[b][rm][k + 4 + qid];
                uint32_t a3 = As[b][rm + 8][k + 4 + qid];
#pragma unroll
                for (int nt = 0; nt < 4; nt++)
                    mma_tf32(acc[mt][nt], a0, a1, a2, a3, bf[nt][0], bf[nt][1]);
            }
        }
        __syncthreads();

        if (kc + 3 < NCHUNK) {              // refill stage b with chunk kc+3
            stsA(b, (kc + 3) & 1);
            cpB(kc + 3, b);
        }
        if (kc + 5 < NCHUNK)                // prefetch chunk kc+5 into freed slot
            ldgA(kc + 5, (kc + 5) & 1);

        b++; if (b == 3) b = 0;
    }

    // Epilogue: bias + relu, float2 pairs
#pragma unroll
    for (int nt = 0; nt < 4; nt++) {
        int col = n0 + warpN * 32 + nt * 8 + 2 * qid;
        float bb0 = __ldg(&bias[col]);
        float bb1 = __ldg(&bias[col + 1]);
#pragma unroll
        for (int mt = 0; mt < 2; mt++) {
            int r0 = m0 + warpM * 32 + mt * 16 + grp;
            if (r0 < M) {
                float2 v = make_float2(fmaxf(acc[mt][nt][0] + bb0, 0.f),
                                       fmaxf(acc[mt][nt][1] + bb1, 0.f));
                *(float2*)&g_hidden[(size_t)r0 * HID_DIM + col] = v;
            }
            if (r0 + 8 < M) {
                float2 v = make_float2(fmaxf(acc[mt][nt][2] + bb0, 0.f),
                                       fmaxf(acc[mt][nt][3] + bb1, 0.f));
                *(float2*)&g_hidden[(size_t)(r0 + 8) * HID_DIM + col] = v;
            }
        }
    }
}

// ---------------------------------------------------------------------------
// GEMM2: h0 = hidden[M,256] @ W2[256,48] + b2  (SIMT)
// ---------------------------------------------------------------------------
__global__ __launch_bounds__(256) void gemm2_kernel(
    const float* __restrict__ W2, const float* __restrict__ b2, int M)
{
    __shared__ float Ws[64][48];
    const int tid = threadIdx.x;
    const int row = blockIdx.x * 128 + (tid >> 1);
    const int half = tid & 1;
    const bool ok = (row < M);

    float acc[24];
#pragma unroll
    for (int j = 0; j < 24; j++) acc[j] = 0.f;

    const float4* hid4 = (const float4*)g_hidden;
    for (int kc = 0; kc < 4; kc++) {
        __syncthreads();
        for (int i = tid; i < 64 * 48; i += 256) {
            int kk = i / 48, c = i - kk * 48;
            Ws[kk][c] = W2[(kc * 64 + kk) * 48 + c];
        }
        __syncthreads();
        if (ok) {
#pragma unroll
            for (int k4 = 0; k4 < 16; k4++) {
                float4 a = hid4[(size_t)row * 64 + kc * 16 + k4];
                float av[4] = {a.x, a.y, a.z, a.w};
#pragma unroll
                for (int q = 0; q < 4; q++)
#pragma unroll
                    for (int j = 0; j < 24; j++)
                        acc[j] += av[q] * Ws[k4 * 4 + q][half * 24 + j];
            }
        }
    }
    if (ok) {
#pragma unroll
        for (int j = 0; j < 24; j++)
            g_h0[(size_t)row * 48 + half * 24 + j] = acc[j] + b2[half * 24 + j];
    }
}

// ---------------------------------------------------------------------------
// Propagation (CSR, fused, atomic-free)
// ---------------------------------------------------------------------------
__global__ void hs0_kernel(int n4) {
    int i = blockIdx.x * blockDim.x + threadIdx.x;
    if (i >= n4) return;
    int row = i / 12;
    float no = g_norm_out[row];
    float4 v = ((const float4*)g_h0)[i];
    ((float4*)g_hsA)[i] = make_float4(v.x * no, v.y * no, v.z * no, v.w * no);
}

__global__ __launch_bounds__(384) void agg_kernel(
    float* __restrict__ dout, int parity, int last, int n)
{
    int t = blockIdx.x * 384 + threadIdx.x;
    int g = t / 12;
    int c = t - g * 12;
    if (g >= n) return;

    const float4* hin  = (const float4*)(parity ? g_hsB : g_hsA);
    float4*       hout = (float4*)(parity ? g_hsA : g_hsB);

    int i   = g_off[g];
    int end = g_off[g + 1];
    float4 acc = make_float4(0.f, 0.f, 0.f, 0.f);

    for (; i + 3 < end; i += 4) {
        int s0 = __ldg(&g_csr_src[i]);
        int s1 = __ldg(&g_csr_src[i + 1]);
        int s2 = __ldg(&g_csr_src[i + 2]);
        int s3 = __ldg(&g_csr_src[i + 3]);
        float4 v0 = hin[(size_t)s0 * 12 + c];
        float4 v1 = hin[(size_t)s1 * 12 + c];
        float4 v2 = hin[(size_t)s2 * 12 + c];
        float4 v3 = hin[(size_t)s3 * 12 + c];
        acc.x += v0.x + v1.x + v2.x + v3.x;
        acc.y += v0.y + v1.y + v2.y + v3.y;
        acc.z += v0.z + v1.z + v2.z + v3.z;
        acc.w += v0.w + v1.w + v2.w + v3.w;
    }
    for (; i < end; i++) {
        int s = __ldg(&g_csr_src[i]);
        float4 v = hin[(size_t)s * 12 + c];
        acc.x += v.x; acc.y += v.y; acc.z += v.z; acc.w += v.w;
    }

    float ni = g_norm_in[g];
    float4 z = ((const float4*)g_h0)[(size_t)g * 12 + c];
    float4 h = make_float4(0.9f * acc.x * ni + 0.1f * z.x,
                           0.9f * acc.y * ni + 0.1f * z.y,
                           0.9f * acc.z * ni + 0.1f * z.z,
                           0.9f * acc.w * ni + 0.1f * z.w);
    if (last) {
        ((float4*)dout)[(size_t)g * 12 + c] = h;
    } else {
        float no = g_norm_out[g];
        hout[(size_t)g * 12 + c] = make_float4(h.x * no, h.y * no, h.z * no, h.w * no);
    }
}

// ---------------------------------------------------------------------------
extern "C" void kernel_launch(void* const* d_in, const int* in_sizes, int n_in,
                              void* d_out, int out_size)
{
    const float* feats = (const float*)d_in[0];
    const int*   src   = (const int*)d_in[1];
    const int*   dst   = (const int*)d_in[2];
    const float* W1    = (const float*)d_in[3];
    const float* b1    = (const float*)d_in[4];
    const float* W2    = (const float*)d_in[5];
    const float* b2    = (const float*)d_in[6];

    const int N = in_sizes[0] / IN_DIM;
    const int E = in_sizes[1];

    // degrees + norms
    zero_deg_kernel<<<(N + 255) / 256, 256>>>(N);
    deg_kernel<<<(E + 255) / 256, 256>>>(src, dst, E);
    norm_kernel<<<(N + 255) / 256, 256>>>(N);

    // CSR build (by dst)
    const int scanBlocks = (N + 255) / 256;
    scanA_kernel<<<scanBlocks, 256>>>(N);
    scanB_kernel<<<1, 512>>>(scanBlocks);
    scanC_kernel<<<scanBlocks, 256>>>(N);
    cursor_init_kernel<<<(N + 255) / 256, 256>>>(N);
    scatter_kernel<<<(E + 255) / 256, 256>>>(src, dst, E);

    // W1 pre-round (tf32 RNA) + MLP
    w1_round_kernel<<<(IN_DIM * HID_DIM + 255) / 256, 256>>>(W1);
    dim3 g1(HID_DIM / 64, (N + 127) / 128);
    gemm1_mma_kernel<<<g1, 256>>>(feats, b1, N);
    gemm2_kernel<<<(N + 127) / 128, 256>>>(W2, b2, N);

    // propagation
    const int n4 = N * 12;
    hs0_kernel<<<(n4 + 255) / 256, 256>>>(n4);
    const int aggBlocks = (N * 12 + 383) / 384;
    for (int k = 0; k < 10; k++) {
        agg_kernel<<<aggBlocks, 384>>>((float*)d_out, k & 1, k == 9 ? 1 : 0, N);
    }
    (void)n_in; (void)out_size;
}

// round 14
// speedup vs baseline: 1.2306x; 1.2306x over previous
#include <cuda_runtime.h>
#include <cstdint>

// ---------------------------------------------------------------------------
// APPNP. GEMM1: tf32 mma.sync, 3-stage cp.async pipeline (exact R8 structure).
// B (W1) pre-rounded to tf32 RNA once (mma's RZ truncation of it = identity);
// A raw-truncated. Propagation: CSR(dst) + fused gather-reduce (R8 form).
// ---------------------------------------------------------------------------

#define N_NODES 100000
#define E_EDGES 1600000
#define OUT_DIM 48
#define HID_DIM 256
#define IN_DIM  512

// Scratch (device globals — allocation APIs are forbidden)
__device__ __align__(16) float g_hidden[(size_t)N_NODES * HID_DIM];
__device__ __align__(16) float g_w1r[(size_t)IN_DIM * HID_DIM];   // RNA-rounded W1
__device__ __align__(16) float g_h0[(size_t)N_NODES * OUT_DIM];
__device__ __align__(16) float g_hsA[(size_t)N_NODES * OUT_DIM];
__device__ __align__(16) float g_hsB[(size_t)N_NODES * OUT_DIM];
__device__ int   g_ideg_out[N_NODES];
__device__ int   g_ideg_in[N_NODES];
__device__ float g_norm_out[N_NODES];
__device__ float g_norm_in[N_NODES];
__device__ int   g_off[N_NODES + 1];
__device__ int   g_cursor[N_NODES];
__device__ int   g_blocksums[512];
__device__ int   g_csr_src[E_EDGES];

// ---------------------------------------------------------------------------
// Degrees / norms
// ---------------------------------------------------------------------------
__global__ void zero_deg_kernel(int n) {
    int i = blockIdx.x * blockDim.x + threadIdx.x;
    if (i < n) { g_ideg_out[i] = 0; g_ideg_in[i] = 0; }
}
__global__ void deg_kernel(const int* __restrict__ src, const int* __restrict__ dst, int e) {
    int i = blockIdx.x * blockDim.x + threadIdx.x;
    if (i < e) {
        atomicAdd(&g_ideg_out[src[i]], 1);
        atomicAdd(&g_ideg_in[dst[i]], 1);
    }
}
__global__ void norm_kernel(int n) {
    int i = blockIdx.x * blockDim.x + threadIdx.x;
    if (i < n) {
        g_norm_out[i] = rsqrtf((float)max(g_ideg_out[i], 1));
        g_norm_in[i]  = rsqrtf((float)max(g_ideg_in[i], 1));
    }
}

// ---------------------------------------------------------------------------
// Prefix sum over g_ideg_in -> g_off
// ---------------------------------------------------------------------------
__global__ void scanA_kernel(int n) {
    __shared__ int sh[256];
    int i = blockIdx.x * 256 + threadIdx.x;
    sh[threadIdx.x] = (i < n) ? g_ideg_in[i] : 0;
    __syncthreads();
#pragma unroll
    for (int d = 1; d < 256; d <<= 1) {
        int t = (threadIdx.x >= d) ? sh[threadIdx.x - d] : 0;
        __syncthreads();
        sh[threadIdx.x] += t;
        __syncthreads();
    }
    if (i < n) g_off[i + 1] = sh[threadIdx.x];
    if (threadIdx.x == 255) g_blocksums[blockIdx.x] = sh[255];
}
__global__ void scanB_kernel(int nb) {
    __shared__ int sh[512];
    int t = threadIdx.x;
    sh[t] = (t < nb) ? g_blocksums[t] : 0;
    __syncthreads();
#pragma unroll
    for (int d = 1; d < 512; d <<= 1) {
        int x = (t >= d) ? sh[t - d] : 0;
        __syncthreads();
        sh[t] += x;
        __syncthreads();
    }
    if (t < nb) g_blocksums[t] = sh[t];
}
__global__ void scanC_kernel(int n) {
    int i = blockIdx.x * 256 + threadIdx.x;
    if (i < n) {
        int add = (blockIdx.x > 0) ? g_blocksums[blockIdx.x - 1] : 0;
        g_off[i + 1] += add;
    }
    if (i == 0) g_off[0] = 0;
}
__global__ void cursor_init_kernel(int n) {
    int i = blockIdx.x * blockDim.x + threadIdx.x;
    if (i < n) g_cursor[i] = g_off[i];
}
__global__ void scatter_kernel(const int* __restrict__ src, const int* __restrict__ dst, int e) {
    int i = blockIdx.x * blockDim.x + threadIdx.x;
    if (i < e) {
        int p = atomicAdd(&g_cursor[dst[i]], 1);
        g_csr_src[p] = src[i];
    }
}

// ---------------------------------------------------------------------------
// tf32 helpers
// ---------------------------------------------------------------------------
__device__ __forceinline__ uint32_t rna_tf32_f(float x) {
    uint32_t u;
    asm("cvt.rna.tf32.f32 %0, %1;" : "=r"(u) : "f"(x));
    return u;
}
__device__ __forceinline__ void mma_tf32(float c[4],
                                         uint32_t a0, uint32_t a1, uint32_t a2, uint32_t a3,
                                         uint32_t b0, uint32_t b1)
{
    asm volatile(
        "mma.sync.aligned.m16n8k8.row.col.f32.tf32.tf32.f32 "
        "{%0,%1,%2,%3}, {%4,%5,%6,%7}, {%8,%9}, {%0,%1,%2,%3};"
        : "+f"(c[0]), "+f"(c[1]), "+f"(c[2]), "+f"(c[3])
        : "r"(a0), "r"(a1), "r"(a2), "r"(a3), "r"(b0), "r"(b1));
}
__device__ __forceinline__ uint32_t smem_u32(const void* p) {
    uint32_t a;
    asm("{ .reg .u64 t; cvta.to.shared.u64 t, %1; cvt.u32.u64 %0, t; }" : "=r"(a) : "l"(p));
    return a;
}
__device__ __forceinline__ void cp16(uint32_t dst, const void* src, int szbytes) {
    asm volatile("cp.async.cg.shared.global [%0], [%1], 16, %2;"
                 :: "r"(dst), "l"(src), "r"(szbytes));
}
#define CP_COMMIT() asm volatile("cp.async.commit_group;" ::: "memory")
#define CP_WAIT(n)  asm volatile("cp.async.wait_group %0;" :: "n"(n) : "memory")

// W1 pre-round (RNA): mma's RZ truncation of this is the identity
__global__ void w1_round_kernel(const float* __restrict__ W1) {
    int i = blockIdx.x * blockDim.x + threadIdx.x;
    if (i < IN_DIM * HID_DIM)
        g_w1r[i] = __uint_as_float(rna_tf32_f(W1[i]));
}

// ---------------------------------------------------------------------------
// GEMM1 (tf32 mma.sync, 3-stage cp.async, static SMEM):
//   hidden = relu(feats[M,512] @ W1[512,256] + b1)
// CTA tile 128x64, 8 warps (4 warpM x 2 warpN), warp tile 32x32.
// K chunks of 16 (2 k-steps of 8 each), 32 chunks total, 3 SMEM buffers.
// ---------------------------------------------------------------------------
#define G1_AS_STRIDE 20
#define G1_BS_STRIDE 72
#define G1_NCHUNK    (IN_DIM / 16)   // 32

__global__ __launch_bounds__(256, 2) void gemm1_mma_kernel(
    const float* __restrict__ A, const float* __restrict__ bias, int M)
{
    __shared__ uint32_t As[3][128][G1_AS_STRIDE];   // 3 * 10240 B
    __shared__ uint32_t Bs[3][16][G1_BS_STRIDE];    // 3 *  4608 B

    const int tid  = threadIdx.x;
    const int wid  = tid >> 5;
    const int lane = tid & 31;
    const int warpM = wid & 3;
    const int warpN = wid >> 2;
    const int m0 = blockIdx.y * 128;
    const int n0 = blockIdx.x * 64;

    const int grp = lane >> 2;
    const int qid = lane & 3;

    const int a_m0  = tid >> 2;
    const int a_k0  = (tid & 3) * 4;
    const int a_m1  = (tid + 256) >> 2;
    const int a_k1  = ((tid + 256) & 3) * 4;
    const int b_kk  = tid >> 4;
    const int b_nn4 = (tid & 15) * 4;

    float acc[2][4][4];
#pragma unroll
    for (int mt = 0; mt < 2; mt++)
#pragma unroll
        for (int nt = 0; nt < 4; nt++)
#pragma unroll
            for (int q = 0; q < 4; q++) acc[mt][nt][q] = 0.f;

    auto issue = [&](int kc, int b) {
        const int k0 = kc * 16;
        const uint32_t abase = smem_u32(&As[b][0][0]);
        const uint32_t bbase = smem_u32(&Bs[b][0][0]);
        int sz0 = (m0 + a_m0 < M) ? 16 : 0;
        cp16(abase + (uint32_t)(a_m0 * G1_AS_STRIDE + a_k0) * 4,
             &A[(size_t)(m0 + a_m0) * IN_DIM + k0 + a_k0], sz0);
        int sz1 = (m0 + a_m1 < M) ? 16 : 0;
        cp16(abase + (uint32_t)(a_m1 * G1_AS_STRIDE + a_k1) * 4,
             &A[(size_t)(m0 + a_m1) * IN_DIM + k0 + a_k1], sz1);
        cp16(bbase + (uint32_t)(b_kk * G1_BS_STRIDE + b_nn4) * 4,
             &g_w1r[(size_t)(k0 + b_kk) * HID_DIM + n0 + b_nn4], 16);
        CP_COMMIT();
    };

    issue(0, 0);
    issue(1, 1);

    int b = 0;
    for (int kc = 0; kc < G1_NCHUNK; kc++) {
        if (kc + 2 < G1_NCHUNK) {
            int nb = b + 2; if (nb >= 3) nb -= 3;
            issue(kc + 2, nb);
            CP_WAIT(2);
        } else if (kc + 1 < G1_NCHUNK) {
            CP_WAIT(1);
        } else {
            CP_WAIT(0);
        }
        __syncthreads();

#pragma unroll
        for (int ks = 0; ks < 2; ks++) {
            const int k = ks * 8;
            uint32_t bf[4][2];
#pragma unroll
            for (int nt = 0; nt < 4; nt++) {
                int cn = warpN * 32 + nt * 8 + grp;
                bf[nt][0] = Bs[b][k + qid][cn];
                bf[nt][1] = Bs[b][k + 4 + qid][cn];
            }
#pragma unroll
            for (int mt = 0; mt < 2; mt++) {
                int rm = warpM * 32 + mt * 16 + grp;
                uint32_t a0 = As[b][rm][k + qid];
                uint32_t a1 = As[b][rm + 8][k + qid];
                uint32_t a2 = As[b][rm][k + 4 + qid];
                uint32_t a3 = As[b][rm + 8][k + 4 + qid];
#pragma unroll
                for (int nt = 0; nt < 4; nt++)
                    mma_tf32(acc[mt][nt], a0, a1, a2, a3, bf[nt][0], bf[nt][1]);
            }
        }
        __syncthreads();
        b++; if (b == 3) b = 0;
    }

    // Epilogue: bias + relu, float2 pairs
#pragma unroll
    for (int nt = 0; nt < 4; nt++) {
        int col = n0 + warpN * 32 + nt * 8 + 2 * qid;
        float bb0 = __ldg(&bias[col]);
        float bb1 = __ldg(&bias[col + 1]);
#pragma unroll
        for (int mt = 0; mt < 2; mt++) {
            int r0 = m0 + warpM * 32 + mt * 16 + grp;
            if (r0 < M) {
                float2 v = make_float2(fmaxf(acc[mt][nt][0] + bb0, 0.f),
                                       fmaxf(acc[mt][nt][1] + bb1, 0.f));
                *(float2*)&g_hidden[(size_t)r0 * HID_DIM + col] = v;
            }
            if (r0 + 8 < M) {
                float2 v = make_float2(fmaxf(acc[mt][nt][2] + bb0, 0.f),
                                       fmaxf(acc[mt][nt][3] + bb1, 0.f));
                *(float2*)&g_hidden[(size_t)(r0 + 8) * HID_DIM + col] = v;
            }
        }
    }
}

// ---------------------------------------------------------------------------
// GEMM2: h0 = hidden[M,256] @ W2[256,48] + b2  (SIMT)
// ---------------------------------------------------------------------------
__global__ __launch_bounds__(256) void gemm2_kernel(
    const float* __restrict__ W2, const float* __restrict__ b2, int M)
{
    __shared__ float Ws[64][48];
    const int tid = threadIdx.x;
    const int row = blockIdx.x * 128 + (tid >> 1);
    const int half = tid & 1;
    const bool ok = (row < M);

    float acc[24];
#pragma unroll
    for (int j = 0; j < 24; j++) acc[j] = 0.f;

    const float4* hid4 = (const float4*)g_hidden;
    for (int kc = 0; kc < 4; kc++) {
        __syncthreads();
        for (int i = tid; i < 64 * 48; i += 256) {
            int kk = i / 48, c = i - kk * 48;
            Ws[kk][c] = W2[(kc * 64 + kk) * 48 + c];
        }
        __syncthreads();
        if (ok) {
#pragma unroll
            for (int k4 = 0; k4 < 16; k4++) {
                float4 a = hid4[(size_t)row * 64 + kc * 16 + k4];
                float av[4] = {a.x, a.y, a.z, a.w};
#pragma unroll
                for (int q = 0; q < 4; q++)
#pragma unroll
                    for (int j = 0; j < 24; j++)
                        acc[j] += av[q] * Ws[k4 * 4 + q][half * 24 + j];
            }
        }
    }
    if (ok) {
#pragma unroll
        for (int j = 0; j < 24; j++)
            g_h0[(size_t)row * 48 + half * 24 + j] = acc[j] + b2[half * 24 + j];
    }
}

// ---------------------------------------------------------------------------
// Propagation (CSR, fused, atomic-free)
// ---------------------------------------------------------------------------
__global__ void hs0_kernel(int n4) {
    int i = blockIdx.x * blockDim.x + threadIdx.x;
    if (i >= n4) return;
    int row = i / 12;
    float no = g_norm_out[row];
    float4 v = ((const float4*)g_h0)[i];
    ((float4*)g_hsA)[i] = make_float4(v.x * no, v.y * no, v.z * no, v.w * no);
}

__global__ __launch_bounds__(384) void agg_kernel(
    float* __restrict__ dout, int parity, int last, int n)
{
    int t = blockIdx.x * 384 + threadIdx.x;
    int g = t / 12;
    int c = t - g * 12;
    if (g >= n) return;

    const float4* hin  = (const float4*)(parity ? g_hsB : g_hsA);
    float4*       hout = (float4*)(parity ? g_hsA : g_hsB);

    int i   = g_off[g];
    int end = g_off[g + 1];
    float4 acc = make_float4(0.f, 0.f, 0.f, 0.f);

    for (; i + 3 < end; i += 4) {
        int s0 = __ldg(&g_csr_src[i]);
        int s1 = __ldg(&g_csr_src[i + 1]);
        int s2 = __ldg(&g_csr_src[i + 2]);
        int s3 = __ldg(&g_csr_src[i + 3]);
        float4 v0 = hin[(size_t)s0 * 12 + c];
        float4 v1 = hin[(size_t)s1 * 12 + c];
        float4 v2 = hin[(size_t)s2 * 12 + c];
        float4 v3 = hin[(size_t)s3 * 12 + c];
        acc.x += v0.x + v1.x + v2.x + v3.x;
        acc.y += v0.y + v1.y + v2.y + v3.y;
        acc.z += v0.z + v1.z + v2.z + v3.z;
        acc.w += v0.w + v1.w + v2.w + v3.w;
    }
    for (; i < end; i++) {
        int s = __ldg(&g_csr_src[i]);
        float4 v = hin[(size_t)s * 12 + c];
        acc.x += v.x; acc.y += v.y; acc.z += v.z; acc.w += v.w;
    }

    float ni = g_norm_in[g];
    float4 z = ((const float4*)g_h0)[(size_t)g * 12 + c];
    float4 h = make_float4(0.9f * acc.x * ni + 0.1f * z.x,
                           0.9f * acc.y * ni + 0.1f * z.y,
                           0.9f * acc.z * ni + 0.1f * z.z,
                           0.9f * acc.w * ni + 0.1f * z.w);
    if (last) {
        ((float4*)dout)[(size_t)g * 12 + c] = h;
    } else {
        float no = g_norm_out[g];
        hout[(size_t)g * 12 + c] = make_float4(h.x * no, h.y * no, h.z * no, h.w * no);
    }
}

// ---------------------------------------------------------------------------
extern "C" void kernel_launch(void* const* d_in, const int* in_sizes, int n_in,
                              void* d_out, int out_size)
{
    const float* feats = (const float*)d_in[0];
    const int*   src   = (const int*)d_in[1];
    const int*   dst   = (const int*)d_in[2];
    const float* W1    = (const float*)d_in[3];
    const float* b1    = (const float*)d_in[4];
    const float* W2    = (const float*)d_in[5];
    const float* b2    = (const float*)d_in[6];

    const int N = in_sizes[0] / IN_DIM;
    const int E = in_sizes[1];

    // degrees + norms
    zero_deg_kernel<<<(N + 255) / 256, 256>>>(N);
    deg_kernel<<<(E + 255) / 256, 256>>>(src, dst, E);
    norm_kernel<<<(N + 255) / 256, 256>>>(N);

    // CSR build (by dst)
    const int scanBlocks = (N + 255) / 256;
    scanA_kernel<<<scanBlocks, 256>>>(N);
    scanB_kernel<<<1, 512>>>(scanBlocks);
    scanC_kernel<<<scanBlocks, 256>>>(N);
    cursor_init_kernel<<<(N + 255) / 256, 256>>>(N);
    scatter_kernel<<<(E + 255) / 256, 256>>>(src, dst, E);

    // W1 pre-round + MLP (static smem only)
    w1_round_kernel<<<(IN_DIM * HID_DIM + 255) / 256, 256>>>(W1);
    dim3 g1(HID_DIM / 64, (N + 127) / 128);
    gemm1_mma_kernel<<<g1, 256>>>(feats, b1, N);
    gemm2_kernel<<<(N + 127) / 128, 256>>>(W2, b2, N);

    // propagation
    const int n4 = N * 12;
    hs0_kernel<<<(n4 + 255) / 256, 256>>>(n4);
    const int aggBlocks = (N * 12 + 383) / 384;
    for (int k = 0; k < 10; k++) {
        agg_kernel<<<aggBlocks, 384>>>((float*)d_out, k & 1, k == 9 ? 1 : 0, N);
    }
    (void)n_in; (void)out_size;
}

// round 15
// speedup vs baseline: 1.3445x; 1.0925x over previous
#include <cuda_runtime.h>
#include <cstdint>

// ---------------------------------------------------------------------------
// APPNP. GEMM1: tf32 mma.sync, CTA tile 128x128 (warp tile 32x64), 2-stage
// cp.async. B (W1) pre-rounded to tf32 RNA once; A raw-truncated.
// Propagation: CSR(dst) + fused gather-reduce (R8/R14 form).
// ---------------------------------------------------------------------------

#define N_NODES 100000
#define E_EDGES 1600000
#define OUT_DIM 48
#define HID_DIM 256
#define IN_DIM  512

// Scratch (device globals — allocation APIs are forbidden)
__device__ __align__(16) float g_hidden[(size_t)N_NODES * HID_DIM];
__device__ __align__(16) float g_w1r[(size_t)IN_DIM * HID_DIM];   // RNA-rounded W1
__device__ __align__(16) float g_h0[(size_t)N_NODES * OUT_DIM];
__device__ __align__(16) float g_hsA[(size_t)N_NODES * OUT_DIM];
__device__ __align__(16) float g_hsB[(size_t)N_NODES * OUT_DIM];
__device__ int   g_ideg_out[N_NODES];
__device__ int   g_ideg_in[N_NODES];
__device__ float g_norm_out[N_NODES];
__device__ float g_norm_in[N_NODES];
__device__ int   g_off[N_NODES + 1];
__device__ int   g_cursor[N_NODES];
__device__ int   g_blocksums[512];
__device__ int   g_csr_src[E_EDGES];

// ---------------------------------------------------------------------------
// Degrees / norms
// ---------------------------------------------------------------------------
__global__ void zero_deg_kernel(int n) {
    int i = blockIdx.x * blockDim.x + threadIdx.x;
    if (i < n) { g_ideg_out[i] = 0; g_ideg_in[i] = 0; }
}
__global__ void deg_kernel(const int* __restrict__ src, const int* __restrict__ dst, int e) {
    int i = blockIdx.x * blockDim.x + threadIdx.x;
    if (i < e) {
        atomicAdd(&g_ideg_out[src[i]], 1);
        atomicAdd(&g_ideg_in[dst[i]], 1);
    }
}
__global__ void norm_kernel(int n) {
    int i = blockIdx.x * blockDim.x + threadIdx.x;
    if (i < n) {
        g_norm_out[i] = rsqrtf((float)max(g_ideg_out[i], 1));
        g_norm_in[i]  = rsqrtf((float)max(g_ideg_in[i], 1));
    }
}

// ---------------------------------------------------------------------------
// Prefix sum over g_ideg_in -> g_off
// ---------------------------------------------------------------------------
__global__ void scanA_kernel(int n) {
    __shared__ int sh[256];
    int i = blockIdx.x * 256 + threadIdx.x;
    sh[threadIdx.x] = (i < n) ? g_ideg_in[i] : 0;
    __syncthreads();
#pragma unroll
    for (int d = 1; d < 256; d <<= 1) {
        int t = (threadIdx.x >= d) ? sh[threadIdx.x - d] : 0;
        __syncthreads();
        sh[threadIdx.x] += t;
        __syncthreads();
    }
    if (i < n) g_off[i + 1] = sh[threadIdx.x];
    if (threadIdx.x == 255) g_blocksums[blockIdx.x] = sh[255];
}
__global__ void scanB_kernel(int nb) {
    __shared__ int sh[512];
    int t = threadIdx.x;
    sh[t] = (t < nb) ? g_blocksums[t] : 0;
    __syncthreads();
#pragma unroll
    for (int d = 1; d < 512; d <<= 1) {
        int x = (t >= d) ? sh[t - d] : 0;
        __syncthreads();
        sh[t] += x;
        __syncthreads();
    }
    if (t < nb) g_blocksums[t] = sh[t];
}
__global__ void scanC_kernel(int n) {
    int i = blockIdx.x * 256 + threadIdx.x;
    if (i < n) {
        int add = (blockIdx.x > 0) ? g_blocksums[blockIdx.x - 1] : 0;
        g_off[i + 1] += add;
    }
    if (i == 0) g_off[0] = 0;
}
__global__ void cursor_init_kernel(int n) {
    int i = blockIdx.x * blockDim.x + threadIdx.x;
    if (i < n) g_cursor[i] = g_off[i];
}
__global__ void scatter_kernel(const int* __restrict__ src, const int* __restrict__ dst, int e) {
    int i = blockIdx.x * blockDim.x + threadIdx.x;
    if (i < e) {
        int p = atomicAdd(&g_cursor[dst[i]], 1);
        g_csr_src[p] = src[i];
    }
}

// ---------------------------------------------------------------------------
// tf32 helpers
// ---------------------------------------------------------------------------
__device__ __forceinline__ uint32_t rna_tf32_f(float x) {
    uint32_t u;
    asm("cvt.rna.tf32.f32 %0, %1;" : "=r"(u) : "f"(x));
    return u;
}
__device__ __forceinline__ void mma_tf32(float c[4],
                                         uint32_t a0, uint32_t a1, uint32_t a2, uint32_t a3,
                                         uint32_t b0, uint32_t b1)
{
    asm volatile(
        "mma.sync.aligned.m16n8k8.row.col.f32.tf32.tf32.f32 "
        "{%0,%1,%2,%3}, {%4,%5,%6,%7}, {%8,%9}, {%0,%1,%2,%3};"
        : "+f"(c[0]), "+f"(c[1]), "+f"(c[2]), "+f"(c[3])
        : "r"(a0), "r"(a1), "r"(a2), "r"(a3), "r"(b0), "r"(b1));
}
__device__ __forceinline__ uint32_t smem_u32(const void* p) {
    uint32_t a;
    asm("{ .reg .u64 t; cvta.to.shared.u64 t, %1; cvt.u32.u64 %0, t; }" : "=r"(a) : "l"(p));
    return a;
}
__device__ __forceinline__ void cp16(uint32_t dst, const void* src, int szbytes) {
    asm volatile("cp.async.cg.shared.global [%0], [%1], 16, %2;"
                 :: "r"(dst), "l"(src), "r"(szbytes));
}
#define CP_COMMIT() asm volatile("cp.async.commit_group;" ::: "memory")
#define CP_WAIT(n)  asm volatile("cp.async.wait_group %0;" :: "n"(n) : "memory")

// W1 pre-round (RNA): mma's RZ truncation of this is the identity
__global__ void w1_round_kernel(const float* __restrict__ W1) {
    int i = blockIdx.x * blockDim.x + threadIdx.x;
    if (i < IN_DIM * HID_DIM)
        g_w1r[i] = __uint_as_float(rna_tf32_f(W1[i]));
}

// ---------------------------------------------------------------------------
// GEMM1 (tf32 mma.sync, 2-stage cp.async, static SMEM):
//   hidden = relu(feats[M,512] @ W1[512,256] + b1)
// CTA tile 128x128, 8 warps (4 warpM x 2 warpN), warp tile 32x64.
// K chunks of 16 (2 k-steps of 8), 32 chunks, 2 SMEM buffers.
// As stride 20 (bank 20*grp+qid all-distinct); Bs stride 136 (bank 8*qid+grp).
// SMEM: 2*(10240 + 8704) = 37888 B < 48 KB.
// ---------------------------------------------------------------------------
#define G1_AS_STRIDE 20
#define G1_BS_STRIDE 136
#define G1_NCHUNK    (IN_DIM / 16)   // 32

__global__ __launch_bounds__(256, 2) void gemm1_mma_kernel(
    const float* __restrict__ A, const float* __restrict__ bias, int M)
{
    __shared__ uint32_t As[2][128][G1_AS_STRIDE];   // 2 * 10240 B
    __shared__ uint32_t Bs[2][16][G1_BS_STRIDE];    // 2 *  8704 B

    const int tid  = threadIdx.x;
    const int wid  = tid >> 5;
    const int lane = tid & 31;
    const int warpM = wid & 3;          // 0..3 -> 32-row slices
    const int warpN = wid >> 2;         // 0..1 -> 64-col slices
    const int m0 = blockIdx.y * 128;
    const int n0 = blockIdx.x * 128;

    const int grp = lane >> 2;          // 0..7
    const int qid = lane & 3;           // 0..3

    // A staging: 512 float4 / 256 thr = 2 per thread
    const int a_m0 = tid >> 2;                  // 0..63
    const int a_k0 = (tid & 3) * 4;
    const int a_m1 = (tid + 256) >> 2;          // 64..127
    const int a_k1 = ((tid + 256) & 3) * 4;
    // B staging: 16 rows x 128 cols = 512 float4 = 2 per thread
    const int b_kk0 = tid >> 5;                 // 0..7
    const int b_nn0 = (tid & 31) * 4;
    const int b_kk1 = (tid + 256) >> 5;         // 8..15
    const int b_nn1 = ((tid + 256) & 31) * 4;

    float acc[2][8][4];
#pragma unroll
    for (int mt = 0; mt < 2; mt++)
#pragma unroll
        for (int nt = 0; nt < 8; nt++)
#pragma unroll
            for (int q = 0; q < 4; q++) acc[mt][nt][q] = 0.f;

    auto issue = [&](int kc, int b) {
        const int k0 = kc * 16;
        const uint32_t abase = smem_u32(&As[b][0][0]);
        const uint32_t bbase = smem_u32(&Bs[b][0][0]);
        int sz0 = (m0 + a_m0 < M) ? 16 : 0;
        cp16(abase + (uint32_t)(a_m0 * G1_AS_STRIDE + a_k0) * 4,
             &A[(size_t)(m0 + a_m0) * IN_DIM + k0 + a_k0], sz0);
        int sz1 = (m0 + a_m1 < M) ? 16 : 0;
        cp16(abase + (uint32_t)(a_m1 * G1_AS_STRIDE + a_k1) * 4,
             &A[(size_t)(m0 + a_m1) * IN_DIM + k0 + a_k1], sz1);
        cp16(bbase + (uint32_t)(b_kk0 * G1_BS_STRIDE + b_nn0) * 4,
             &g_w1r[(size_t)(k0 + b_kk0) * HID_DIM + n0 + b_nn0], 16);
        cp16(bbase + (uint32_t)(b_kk1 * G1_BS_STRIDE + b_nn1) * 4,
             &g_w1r[(size_t)(k0 + b_kk1) * HID_DIM + n0 + b_nn1], 16);
        CP_COMMIT();
    };

    issue(0, 0);
    issue(1, 1);

    for (int kc = 0; kc < G1_NCHUNK; kc++) {
        const int b = kc & 1;
        if (kc + 1 < G1_NCHUNK) { CP_WAIT(1); } else { CP_WAIT(0); }
        __syncthreads();

#pragma unroll
        for (int ks = 0; ks < 2; ks++) {
            const int k = ks * 8;
            uint32_t bf[8][2];
#pragma unroll
            for (int nt = 0; nt < 8; nt++) {
                int cn = warpN * 64 + nt * 8 + grp;
                bf[nt][0] = Bs[b][k + qid][cn];
                bf[nt][1] = Bs[b][k + 4 + qid][cn];
            }
#pragma unroll
            for (int mt = 0; mt < 2; mt++) {
                int rm = warpM * 32 + mt * 16 + grp;
                uint32_t a0 = As[b][rm][k + qid];
                uint32_t a1 = As[b][rm + 8][k + qid];
                uint32_t a2 = As[b][rm][k + 4 + qid];
                uint32_t a3 = As[b][rm + 8][k + 4 + qid];
#pragma unroll
                for (int nt = 0; nt < 8; nt++)
                    mma_tf32(acc[mt][nt], a0, a1, a2, a3, bf[nt][0], bf[nt][1]);
            }
        }
        __syncthreads();
        if (kc + 2 < G1_NCHUNK) issue(kc + 2, b);
    }

    // Epilogue: bias + relu, float2 pairs
#pragma unroll
    for (int nt = 0; nt < 8; nt++) {
        int col = n0 + warpN * 64 + nt * 8 + 2 * qid;
        float bb0 = __ldg(&bias[col]);
        float bb1 = __ldg(&bias[col + 1]);
#pragma unroll
        for (int mt = 0; mt < 2; mt++) {
            int r0 = m0 + warpM * 32 + mt * 16 + grp;
            if (r0 < M) {
                float2 v = make_float2(fmaxf(acc[mt][nt][0] + bb0, 0.f),
                                       fmaxf(acc[mt][nt][1] + bb1, 0.f));
                *(float2*)&g_hidden[(size_t)r0 * HID_DIM + col] = v;
            }
            if (r0 + 8 < M) {
                float2 v = make_float2(fmaxf(acc[mt][nt][2] + bb0, 0.f),
                                       fmaxf(acc[mt][nt][3] + bb1, 0.f));
                *(float2*)&g_hidden[(size_t)(r0 + 8) * HID_DIM + col] = v;
            }
        }
    }
}

// ---------------------------------------------------------------------------
// GEMM2: h0 = hidden[M,256] @ W2[256,48] + b2  (SIMT)
// ---------------------------------------------------------------------------
__global__ __launch_bounds__(256) void gemm2_kernel(
    const float* __restrict__ W2, const float* __restrict__ b2, int M)
{
    __shared__ float Ws[64][48];
    const int tid = threadIdx.x;
    const int row = blockIdx.x * 128 + (tid >> 1);
    const int half = tid & 1;
    const bool ok = (row < M);

    float acc[24];
#pragma unroll
    for (int j = 0; j < 24; j++) acc[j] = 0.f;

    const float4* hid4 = (const float4*)g_hidden;
    for (int kc = 0; kc < 4; kc++) {
        __syncthreads();
        for (int i = tid; i < 64 * 48; i += 256) {
            int kk = i / 48, c = i - kk * 48;
            Ws[kk][c] = W2[(kc * 64 + kk) * 48 + c];
        }
        __syncthreads();
        if (ok) {
#pragma unroll
            for (int k4 = 0; k4 < 16; k4++) {
                float4 a = hid4[(size_t)row * 64 + kc * 16 + k4];
                float av[4] = {a.x, a.y, a.z, a.w};
#pragma unroll
                for (int q = 0; q < 4; q++)
#pragma unroll
                    for (int j = 0; j < 24; j++)
                        acc[j] += av[q] * Ws[k4 * 4 + q][half * 24 + j];
            }
        }
    }
    if (ok) {
#pragma unroll
        for (int j = 0; j < 24; j++)
            g_h0[(size_t)row * 48 + half * 24 + j] = acc[j] + b2[half * 24 + j];
    }
}

// ---------------------------------------------------------------------------
// Propagation (CSR, fused, atomic-free)
// ---------------------------------------------------------------------------
__global__ void hs0_kernel(int n4) {
    int i = blockIdx.x * blockDim.x + threadIdx.x;
    if (i >= n4) return;
    int row = i / 12;
    float no = g_norm_out[row];
    float4 v = ((const float4*)g_h0)[i];
    ((float4*)g_hsA)[i] = make_float4(v.x * no, v.y * no, v.z * no, v.w * no);
}

__global__ __launch_bounds__(384) void agg_kernel(
    float* __restrict__ dout, int parity, int last, int n)
{
    int t = blockIdx.x * 384 + threadIdx.x;
    int g = t / 12;
    int c = t - g * 12;
    if (g >= n) return;

    const float4* hin  = (const float4*)(parity ? g_hsB : g_hsA);
    float4*       hout = (float4*)(parity ? g_hsA : g_hsB);

    int i   = g_off[g];
    int end = g_off[g + 1];
    float4 acc = make_float4(0.f, 0.f, 0.f, 0.f);

    for (; i + 3 < end; i += 4) {
        int s0 = __ldg(&g_csr_src[i]);
        int s1 = __ldg(&g_csr_src[i + 1]);
        int s2 = __ldg(&g_csr_src[i + 2]);
        int s3 = __ldg(&g_csr_src[i + 3]);
        float4 v0 = hin[(size_t)s0 * 12 + c];
        float4 v1 = hin[(size_t)s1 * 12 + c];
        float4 v2 = hin[(size_t)s2 * 12 + c];
        float4 v3 = hin[(size_t)s3 * 12 + c];
        acc.x += v0.x + v1.x + v2.x + v3.x;
        acc.y += v0.y + v1.y + v2.y + v3.y;
        acc.z += v0.z + v1.z + v2.z + v3.z;
        acc.w += v0.w + v1.w + v2.w + v3.w;
    }
    for (; i < end; i++) {
        int s = __ldg(&g_csr_src[i]);
        float4 v = hin[(size_t)s * 12 + c];
        acc.x += v.x; acc.y += v.y; acc.z += v.z; acc.w += v.w;
    }

    float ni = g_norm_in[g];
    float4 z = ((const float4*)g_h0)[(size_t)g * 12 + c];
    float4 h = make_float4(0.9f * acc.x * ni + 0.1f * z.x,
                           0.9f * acc.y * ni + 0.1f * z.y,
                           0.9f * acc.z * ni + 0.1f * z.z,
                           0.9f * acc.w * ni + 0.1f * z.w);
    if (last) {
        ((float4*)dout)[(size_t)g * 12 + c] = h;
    } else {
        float no = g_norm_out[g];
        hout[(size_t)g * 12 + c] = make_float4(h.x * no, h.y * no, h.z * no, h.w * no);
    }
}

// ---------------------------------------------------------------------------
extern "C" void kernel_launch(void* const* d_in, const int* in_sizes, int n_in,
                              void* d_out, int out_size)
{
    const float* feats = (const float*)d_in[0];
    const int*   src   = (const int*)d_in[1];
    const int*   dst   = (const int*)d_in[2];
    const float* W1    = (const float*)d_in[3];
    const float* b1    = (const float*)d_in[4];
    const float* W2    = (const float*)d_in[5];
    const float* b2    = (const float*)d_in[6];

    const int N = in_sizes[0] / IN_DIM;
    const int E = in_sizes[1];

    // degrees + norms
    zero_deg_kernel<<<(N + 255) / 256, 256>>>(N);
    deg_kernel<<<(E + 255) / 256, 256>>>(src, dst, E);
    norm_kernel<<<(N + 255) / 256, 256>>>(N);

    // CSR build (by dst)
    const int scanBlocks = (N + 255) / 256;
    scanA_kernel<<<scanBlocks, 256>>>(N);
    scanB_kernel<<<1, 512>>>(scanBlocks);
    scanC_kernel<<<scanBlocks, 256>>>(N);
    cursor_init_kernel<<<(N + 255) / 256, 256>>>(N);
    scatter_kernel<<<(E + 255) / 256, 256>>>(src, dst, E);

    // W1 pre-round + MLP (static smem only)
    w1_round_kernel<<<(IN_DIM * HID_DIM + 255) / 256, 256>>>(W1);
    dim3 g1(HID_DIM / 128, (N + 127) / 128);
    gemm1_mma_kernel<<<g1, 256>>>(feats, b1, N);
    gemm2_kernel<<<(N + 127) / 128, 256>>>(W2, b2, N);

    // propagation
    const int n4 = N * 12;
    hs0_kernel<<<(n4 + 255) / 256, 256>>>(n4);
    const int aggBlocks = (N * 12 + 383) / 384;
    for (int k = 0; k < 10; k++) {
        agg_kernel<<<aggBlocks, 384>>>((float*)d_out, k & 1, k == 9 ? 1 : 0, N);
    }
    (void)n_in; (void)out_size;
}